// round 7
// baseline (speedup 1.0000x reference)
#include <cuda_runtime.h>
#include <math.h>

#define NN 40000
#define EE 640000
#define D  128
#define DOUT 40
#define GR 64
#define SCB 160               // scan blocks (160*256 >= NN)

// ---------------- scratch ----------------------------------------------------
__device__ int   g_degIN[NN];    // zero-initialized at module load; self-cleaning
__device__ int   g_degOUT[NN];
__device__ float g_dis[NN];
__device__ int   g_rowptrO[NN + 1];   // CSR by src
__device__ int   g_cursorO[NN];
__device__ int   g_cdst[EE];
__device__ float g_cnorm[EE];
__device__ float g_h [NN * D];
__device__ float g_y [NN * D];
__device__ float g_h3[NN * DOUT];
__device__ float g_y3[NN * DOUT];
__device__ int   g_part[SCB];
__device__ int   g_poff[SCB];
__device__ unsigned int g_reg;

// ---------------- degrees (in for norm, out for CSR) --------------------------
__global__ void k_deg2(const int* __restrict__ src, const int* __restrict__ dst, int E) {
    int e = blockIdx.x * blockDim.x + threadIdx.x;
    if (e >= E) return;
    atomicAdd(&g_degIN[dst[e]], 1);
    atomicAdd(&g_degOUT[src[e]], 1);
}

// ---------------- 3-phase scan on degOUT ---------------------------------------
__global__ void k_scan_part(int n) {
    __shared__ int sm[256];
    int i = blockIdx.x * 256 + threadIdx.x;
    int v = (i < n) ? g_degOUT[i] : 0;
    sm[threadIdx.x] = v;
    __syncthreads();
#pragma unroll
    for (int o = 128; o; o >>= 1) {
        if (threadIdx.x < o) sm[threadIdx.x] += sm[threadIdx.x + o];
        __syncthreads();
    }
    if (threadIdx.x == 0) g_part[blockIdx.x] = sm[0];
}

__global__ void k_scan_top() {
    __shared__ int sm[256];
    int t = threadIdx.x;
    sm[t] = (t < SCB) ? g_part[t] : 0;
    __syncthreads();
    for (int o = 1; o < 256; o <<= 1) {
        int v = (t >= o) ? sm[t - o] : 0;
        __syncthreads();
        sm[t] += v;
        __syncthreads();
    }
    if (t < SCB) g_poff[t] = sm[t] - g_part[t];
    if (t == 0) g_reg = 0u;
}

__global__ void k_scan_down(int n, int E) {
    __shared__ int sm[256];
    int t = threadIdx.x;
    int i = blockIdx.x * 256 + t;
    int v = (i < n) ? g_degOUT[i] : 0;
    sm[t] = v;
    __syncthreads();
    for (int o = 1; o < 256; o <<= 1) {
        int u = (t >= o) ? sm[t - o] : 0;
        __syncthreads();
        sm[t] += u;
        __syncthreads();
    }
    if (i < n) {
        int excl = g_poff[blockIdx.x] + sm[t] - v;
        g_rowptrO[i] = excl;
        g_cursorO[i] = excl;
        g_dis[i] = rsqrtf((float)(g_degIN[i] + 1));   // in-degree + self loop
        g_degIN[i]  = 0;                              // self-clean for next call
        g_degOUT[i] = 0;
        if (i == n - 1) g_rowptrO[n] = E;
    }
}

// ---------------- CSR-by-src scatter --------------------------------------------
__global__ void k_scatterO(const int* __restrict__ src, const int* __restrict__ dst, int E) {
    int e = blockIdx.x * blockDim.x + threadIdx.x;
    if (e >= E) return;
    int s = src[e], d = dst[e];
    int pos = atomicAdd(&g_cursorO[s], 1);
    g_cdst[pos]  = d;
    g_cnorm[pos] = g_dis[s] * g_dis[d];
}

// ---------------- reg_loss: count reverse edges via src-CSR ---------------------
// edge (s,d): multiplicity of (d,s) = occurrences of s in row d (edges out of d)
__global__ void k_reg(const int* __restrict__ src, const int* __restrict__ dst, int E) {
    int e = blockIdx.x * blockDim.x + threadIdx.x;
    if (e >= E) return;
    int s = src[e], d = dst[e];
    int p  = g_rowptrO[d];
    int pe = g_rowptrO[d + 1];
    int c = 0;
    for (; p < pe; p++) c += (g_cdst[p] == s);
    if (c) atomicAdd(&g_reg, (unsigned int)c);
}

// ---------------- SGEMM [M,128]@[128,128]; optional ReLU(x+b) on load;
//                  epilogue writes H and Yinit = dis^2 * H ----------------------
__global__ __launch_bounds__(256) void k_gemm128(const float* __restrict__ X,
                                                 const float* __restrict__ W,
                                                 const float* __restrict__ bias,
                                                 int act,
                                                 float* __restrict__ H,
                                                 float* __restrict__ Yinit, int M) {
    extern __shared__ float smf[];
    float* Ws = smf;            // D*D
    float* Xs = smf + D * D;    // GR*D
    __shared__ float4 bs4[32];
    for (int i = threadIdx.x; i < D * D; i += 256) Ws[i] = W[i];
    if (threadIdx.x < 32)
        bs4[threadIdx.x] = act ? ((const float4*)bias)[threadIdx.x]
                               : make_float4(0.f, 0.f, 0.f, 0.f);

    const int tx = threadIdx.x & 31;
    const int ty = threadIdx.x >> 5;
    const int t0 = blockIdx.x * GR;     // exactly one tile per block (grid=625)

    __syncthreads();
    const float4* Xg = (const float4*)(X + (size_t)t0 * D);
    float4* Xs4 = (float4*)Xs;
    for (int i = threadIdx.x; i < GR * (D / 4); i += 256) {
        float4 xv = Xg[i];
        if (act) {
            float4 bb = bs4[i & 31];
            xv.x = fmaxf(xv.x + bb.x, 0.f);
            xv.y = fmaxf(xv.y + bb.y, 0.f);
            xv.z = fmaxf(xv.z + bb.z, 0.f);
            xv.w = fmaxf(xv.w + bb.w, 0.f);
        }
        Xs4[i] = xv;
    }
    __syncthreads();

    float4 acc[8];
#pragma unroll
    for (int r = 0; r < 8; r++) acc[r] = make_float4(0.f, 0.f, 0.f, 0.f);

    const float* xrow = Xs + ty * 8 * D;
#pragma unroll 4
    for (int k = 0; k < D; k++) {
        float4 wv = *(const float4*)&Ws[k * D + tx * 4];
#pragma unroll
        for (int r = 0; r < 8; r++) {
            float xv = xrow[r * D + k];
            acc[r].x += xv * wv.x;
            acc[r].y += xv * wv.y;
            acc[r].z += xv * wv.z;
            acc[r].w += xv * wv.w;
        }
    }
    float4* Hg = (float4*)(H + (size_t)t0 * D);
    float4* Yg = (float4*)(Yinit + (size_t)t0 * D);
#pragma unroll
    for (int r = 0; r < 8; r++) {
        int row = ty * 8 + r;
        float d2 = g_dis[t0 + row]; d2 *= d2;
        Hg[row * 32 + tx] = acc[r];
        float4 yv = acc[r];
        yv.x *= d2; yv.y *= d2; yv.z *= d2; yv.w *= d2;
        Yg[row * 32 + tx] = yv;
    }
}

// ---------------- SGEMM [M,128]@[128,40]; ReLU(x+b) on load; epilogue H3+Y3 -----
__global__ __launch_bounds__(256) void k_gemm40(const float* __restrict__ X,
                                                const float* __restrict__ W,
                                                const float* __restrict__ bias,
                                                float* __restrict__ H3,
                                                float* __restrict__ Y3, int M) {
    __shared__ float Ws[D * DOUT];
    __shared__ float Xs[GR * D];
    __shared__ float4 bs4[32];
    for (int i = threadIdx.x; i < D * DOUT; i += 256) Ws[i] = W[i];
    if (threadIdx.x < 32) bs4[threadIdx.x] = ((const float4*)bias)[threadIdx.x];

    const int tx = threadIdx.x & 7;
    const int ty = threadIdx.x >> 3;
    const int t0 = blockIdx.x * GR;

    __syncthreads();
    const float4* Xg = (const float4*)(X + (size_t)t0 * D);
    float4* Xs4 = (float4*)Xs;
    for (int i = threadIdx.x; i < GR * (D / 4); i += 256) {
        float4 xv = Xg[i];
        float4 bb = bs4[i & 31];
        xv.x = fmaxf(xv.x + bb.x, 0.f);
        xv.y = fmaxf(xv.y + bb.y, 0.f);
        xv.z = fmaxf(xv.z + bb.z, 0.f);
        xv.w = fmaxf(xv.w + bb.w, 0.f);
        Xs4[i] = xv;
    }
    __syncthreads();

    float a0[5] = {0, 0, 0, 0, 0};
    float a1[5] = {0, 0, 0, 0, 0};
    const float* x0 = Xs + (ty * 2) * D;
#pragma unroll 4
    for (int k = 0; k < D; k++) {
        float w[5];
#pragma unroll
        for (int j = 0; j < 5; j++) w[j] = Ws[k * DOUT + tx * 5 + j];
        float xa = x0[k];
        float xb = x0[D + k];
#pragma unroll
        for (int j = 0; j < 5; j++) {
            a0[j] += xa * w[j];
            a1[j] += xb * w[j];
        }
    }
    int r0 = t0 + ty * 2;
    float d20 = g_dis[r0];     d20 *= d20;
    float d21 = g_dis[r0 + 1]; d21 *= d21;
    float* o0 = H3 + (size_t)r0 * DOUT + tx * 5;
    float* y0 = Y3 + (size_t)r0 * DOUT + tx * 5;
#pragma unroll
    for (int j = 0; j < 5; j++) {
        o0[j] = a0[j];          o0[DOUT + j] = a1[j];
        y0[j] = d20 * a0[j];    y0[DOUT + j] = d21 * a1[j];
    }
}

// ---------------- push aggregation (128-d): stream H rows, REDG into Y ---------
__global__ __launch_bounds__(256) void k_push128(const float* __restrict__ Hh,
                                                 float* __restrict__ Y, int n) {
    const int lane = threadIdx.x & 31;
    const int s = blockIdx.x * 8 + (threadIdx.x >> 5);   // warp per src row
    if (s >= n) return;

    int p  = g_rowptrO[s];
    const int pe = g_rowptrO[s + 1];
    if (p == pe) return;

    const float4 v = ((const float4*)Hh)[(size_t)s * 32 + lane];
    for (; p < pe; p++) {
        int   d = g_cdst[p];        // warp-uniform
        float w = g_cnorm[p];
        float* dptr = Y + (size_t)d * D + lane * 4;
        atomicAdd(dptr + 0, w * v.x);
        atomicAdd(dptr + 1, w * v.y);
        atomicAdd(dptr + 2, w * v.z);
        atomicAdd(dptr + 3, w * v.w);
    }
}

// ---------------- push aggregation (40-d) ---------------------------------------
__global__ __launch_bounds__(256) void k_push40(const float* __restrict__ H3,
                                                float* __restrict__ Y3, int n) {
    const int lane = threadIdx.x & 31;
    const int s = blockIdx.x * 8 + (threadIdx.x >> 5);
    if (s >= n) return;

    int p  = g_rowptrO[s];
    const int pe = g_rowptrO[s + 1];
    if (p == pe) return;

    float v0 = H3[(size_t)s * DOUT + lane];
    float v1 = (lane < 8) ? H3[(size_t)s * DOUT + 32 + lane] : 0.f;
    for (; p < pe; p++) {
        int   d = g_cdst[p];
        float w = g_cnorm[p];
        atomicAdd(&Y3[(size_t)d * DOUT + lane], w * v0);
        if (lane < 8) atomicAdd(&Y3[(size_t)d * DOUT + 32 + lane], w * v1);
    }
}

// ---------------- final: bias + log_softmax + reg --------------------------------
__global__ __launch_bounds__(256) void k_final(const float* __restrict__ Y3,
                                               const float* __restrict__ b,
                                               float* __restrict__ out, int n,
                                               int reg_idx) {
    if (blockIdx.x == 0 && threadIdx.x == 0) out[reg_idx] = (float)g_reg;

    const int lane = threadIdx.x & 31;
    const int i = blockIdx.x * 8 + (threadIdx.x >> 5);
    if (i >= n) return;

    float v0 = Y3[(size_t)i * DOUT + lane] + b[lane];
    float v1 = (lane < 8) ? (Y3[(size_t)i * DOUT + 32 + lane] + b[32 + lane]) : -INFINITY;

    float m = fmaxf(v0, v1);
#pragma unroll
    for (int o = 16; o; o >>= 1) m = fmaxf(m, __shfl_xor_sync(0xffffffffu, m, o));
    float se = expf(v0 - m) + ((lane < 8) ? expf(v1 - m) : 0.f);
#pragma unroll
    for (int o = 16; o; o >>= 1) se += __shfl_xor_sync(0xffffffffu, se, o);
    float ls = m + logf(se);

    out[(size_t)i * DOUT + lane] = v0 - ls;
    if (lane < 8) out[(size_t)i * DOUT + 32 + lane] = v1 - ls;
}

// ---------------- launch -----------------------------------------------------------
extern "C" void kernel_launch(void* const* d_in, const int* in_sizes, int n_in,
                              void* d_out, int out_size) {
    const float* x  = (const float*)d_in[0];
    const int*   ei = (const int*)d_in[1];
    const float* W1 = (const float*)d_in[2];
    const float* b1 = (const float*)d_in[3];
    const float* W2 = (const float*)d_in[4];
    const float* b2 = (const float*)d_in[5];
    const float* W3 = (const float*)d_in[6];
    const float* b3 = (const float*)d_in[7];
    float* out = (float*)d_out;

    const int n = in_sizes[0] / D;      // 40000
    const int E = in_sizes[1] / 2;      // 640000
    const int* src = ei;
    const int* dst = ei + E;

    const int GEMM_SMEM = (D * D + GR * D) * sizeof(float);  // 96 KB
    cudaFuncSetAttribute(k_gemm128, cudaFuncAttributeMaxDynamicSharedMemorySize, GEMM_SMEM);

    const int TB = 256;
    const int eblocks = (E + TB - 1) / TB;
    const int ablocks = (n + 7) / 8;            // warp per node/row
    const int gblocks = (n + GR - 1) / GR;      // 625 (exact tiles)

    // graph structure (degIN/degOUT are zero on entry; scan_down re-zeros them)
    k_deg2<<<eblocks, TB>>>(src, dst, E);
    k_scan_part<<<SCB, 256>>>(n);
    k_scan_top<<<1, 256>>>();
    k_scan_down<<<SCB, 256>>>(n, E);
    k_scatterO<<<eblocks, TB>>>(src, dst, E);
    k_reg<<<eblocks, TB>>>(src, dst, E);

    // layer 1: h = x@W1 ; y = d2*h (init) ; push
    k_gemm128<<<gblocks, TB, GEMM_SMEM>>>(x, W1, b1, 0, g_h, g_y, n);
    k_push128<<<ablocks, TB>>>(g_h, g_y, n);
    // layer 2: h = relu(y+b1)@W2 ; y = d2*h ; push
    k_gemm128<<<gblocks, TB, GEMM_SMEM>>>(g_y, W2, b1, 1, g_h, g_y, n);
    k_push128<<<ablocks, TB>>>(g_h, g_y, n);
    // layer 3: h3 = relu(y+b2)@W3 ; y3 = d2*h3 ; push ; softmax
    k_gemm40<<<gblocks, TB>>>(g_y, W3, b2, g_h3, g_y3, n);
    k_push40<<<ablocks, TB>>>(g_h3, g_y3, n);
    k_final<<<ablocks, TB>>>(g_y3, b3, out, n, out_size - 1);
}

// round 8
// speedup vs baseline: 8.5162x; 8.5162x over previous
#include <cuda_runtime.h>
#include <cuda_fp16.h>
#include <math.h>

#define NN 40000
#define EE 640000
#define D  128
#define DOUT 40
#define GR 64
#define GBB 160               // graph-build blocks (160*250 = 40000 nodes)
#define PER 250               // nodes per graph-build block

// ---------------- scratch ----------------------------------------------------
__device__ int     g_degD[NN];        // in-degree by dst (self-cleaning)
__device__ float   g_dis[NN];
__device__ int     g_rowptr[NN + 1];  // CSR by dst
__device__ int     g_cursor[NN];
__device__ int     g_csrc[EE];
__device__ float   g_cnorm[EE];
__device__ __half2 g_hH[NN * (D / 2)];   // fp16 hidden (gather operand), 256B/row
__device__ float   g_y [NN * D];
__device__ float   g_h3[NN * DOUT];
__device__ int     g_part[GBB];
__device__ int     g_gbar[4];
__device__ unsigned int g_reg;

// ---------------- edge pass: in-degree histogram + reset flags ----------------
__global__ void k_deg(const int* __restrict__ dst, int E) {
    int e = blockIdx.x * blockDim.x + threadIdx.x;
    if (e == 0) { g_gbar[0] = 0; g_gbar[1] = 0; g_gbar[2] = 0; g_reg = 0u; }
    if (e < E) atomicAdd(&g_degD[dst[e]], 1);
}

// software grid barrier (all GBB blocks resident: 160 blocks x 256 thr, tiny smem)
__device__ __forceinline__ void grid_bar(int slot) {
    __syncthreads();
    if (threadIdx.x == 0) {
        __threadfence();
        atomicAdd(&g_gbar[slot], 1);
        while (atomicAdd(&g_gbar[slot], 0) < GBB) { }
        __threadfence();
    }
    __syncthreads();
}

// ---------------- fused graph build: scan -> scatter -> reverse count ---------
__global__ __launch_bounds__(256) void k_graph(const int* __restrict__ src,
                                               const int* __restrict__ dst,
                                               int E, int n) {
    const int tid = threadIdx.x;
    const int bid = blockIdx.x;
    __shared__ int sm[256];
    __shared__ int sp[256];
    __shared__ int s_boff;

    // phase 1: per-block partial sum of degrees over node range [lo, lo+PER)
    const int lo = bid * PER;
    int v = (tid < PER) ? g_degD[lo + tid] : 0;
    sm[tid] = v;
    __syncthreads();
#pragma unroll
    for (int o = 128; o; o >>= 1) {
        if (tid < o) sm[tid] += sm[tid + o];
        __syncthreads();
    }
    if (tid == 0) g_part[bid] = sm[0];
    grid_bar(0);

    // phase 2a: block offset via smem scan of g_part
    sp[tid] = (tid < GBB) ? g_part[tid] : 0;
    __syncthreads();
    for (int o = 1; o < 256; o <<= 1) {
        int u = (tid >= o) ? sp[tid - o] : 0;
        __syncthreads();
        sp[tid] += u;
        __syncthreads();
    }
    if (tid == 0) s_boff = (bid == 0) ? 0 : sp[bid - 1];
    __syncthreads();
    const int boff = s_boff;

    // phase 2b: local inclusive scan of this block's PER degrees
    sm[tid] = v;
    __syncthreads();
    for (int o = 1; o < 256; o <<= 1) {
        int u = (tid >= o) ? sm[tid - o] : 0;
        __syncthreads();
        sm[tid] += u;
        __syncthreads();
    }
    if (tid < PER) {
        int i = lo + tid;
        int excl = boff + sm[tid] - v;
        g_rowptr[i] = excl;
        g_cursor[i] = excl;
        g_dis[i] = rsqrtf((float)(v + 1));   // in-degree + self loop
        g_degD[i] = 0;                       // self-clean for next call
    }
    if (bid == GBB - 1 && tid == 0) g_rowptr[n] = E;
    grid_bar(1);

    // phase 3: CSR scatter (by dst)
    const int gt = bid * 256 + tid;
    const int gs = GBB * 256;
    for (int e = gt; e < E; e += gs) {
        int s = src[e], d = dst[e];
        int pos = atomicAdd(&g_cursor[d], 1);
        g_csrc[pos]  = s;
        g_cnorm[pos] = g_dis[s] * g_dis[d];
    }
    grid_bar(2);

    // phase 4: reg_loss — for edge (s,d), count d among srcs of edges into s
    for (int e = gt; e < E; e += gs) {
        int s = src[e], d = dst[e];
        int p  = g_rowptr[s];
        int pe = g_rowptr[s + 1];
        int c = 0;
        for (; p < pe; p++) c += (g_csrc[p] == d);
        if (c) atomicAdd(&g_reg, (unsigned int)c);
    }
}

// ---------------- SGEMM [M,128]@[128,128]; optional ReLU(x+b) on load;
//                  writes fp16 H (half2) -------------------------------------
__global__ __launch_bounds__(256) void k_gemm128(const float* __restrict__ X,
                                                 const float* __restrict__ W,
                                                 const float* __restrict__ bias,
                                                 int act,
                                                 __half2* __restrict__ Hh, int M) {
    extern __shared__ float smf[];
    float* Ws = smf;            // D*D
    float* Xs = smf + D * D;    // GR*D
    __shared__ float4 bs4[32];
    for (int i = threadIdx.x; i < D * D; i += 256) Ws[i] = W[i];
    if (threadIdx.x < 32)
        bs4[threadIdx.x] = act ? ((const float4*)bias)[threadIdx.x]
                               : make_float4(0.f, 0.f, 0.f, 0.f);

    const int tx = threadIdx.x & 31;
    const int ty = threadIdx.x >> 5;
    const int t0 = blockIdx.x * GR;     // grid = 625 exact tiles

    __syncthreads();
    const float4* Xg = (const float4*)(X + (size_t)t0 * D);
    float4* Xs4 = (float4*)Xs;
    for (int i = threadIdx.x; i < GR * (D / 4); i += 256) {
        float4 xv = Xg[i];
        if (act) {
            float4 bb = bs4[i & 31];
            xv.x = fmaxf(xv.x + bb.x, 0.f);
            xv.y = fmaxf(xv.y + bb.y, 0.f);
            xv.z = fmaxf(xv.z + bb.z, 0.f);
            xv.w = fmaxf(xv.w + bb.w, 0.f);
        }
        Xs4[i] = xv;
    }
    __syncthreads();

    float4 acc[8];
#pragma unroll
    for (int r = 0; r < 8; r++) acc[r] = make_float4(0.f, 0.f, 0.f, 0.f);

    const float* xrow = Xs + ty * 8 * D;
#pragma unroll 4
    for (int k = 0; k < D; k++) {
        float4 wv = *(const float4*)&Ws[k * D + tx * 4];
#pragma unroll
        for (int r = 0; r < 8; r++) {
            float xv = xrow[r * D + k];
            acc[r].x += xv * wv.x;
            acc[r].y += xv * wv.y;
            acc[r].z += xv * wv.z;
            acc[r].w += xv * wv.w;
        }
    }
    // epilogue: fp32 -> fp16, 4 cols per lane = 2 half2
    uint2* Hg = (uint2*)Hh;   // one uint2 = 2 half2 = 4 halfs
#pragma unroll
    for (int r = 0; r < 8; r++) {
        int row = t0 + ty * 8 + r;
        __half2 h01 = __floats2half2_rn(acc[r].x, acc[r].y);
        __half2 h23 = __floats2half2_rn(acc[r].z, acc[r].w);
        uint2 u;
        u.x = *(unsigned int*)&h01;
        u.y = *(unsigned int*)&h23;
        Hg[(size_t)row * 32 + tx] = u;
    }
}

// ---------------- SGEMM [M,128]@[128,40]; ReLU(x+b) on load -------------------
__global__ __launch_bounds__(256) void k_gemm40(const float* __restrict__ X,
                                                const float* __restrict__ W,
                                                const float* __restrict__ bias,
                                                float* __restrict__ H3, int M) {
    __shared__ float Ws[D * DOUT];
    __shared__ float Xs[GR * D];
    __shared__ float4 bs4[32];
    for (int i = threadIdx.x; i < D * DOUT; i += 256) Ws[i] = W[i];
    if (threadIdx.x < 32) bs4[threadIdx.x] = ((const float4*)bias)[threadIdx.x];

    const int tx = threadIdx.x & 7;
    const int ty = threadIdx.x >> 3;
    const int t0 = blockIdx.x * GR;

    __syncthreads();
    const float4* Xg = (const float4*)(X + (size_t)t0 * D);
    float4* Xs4 = (float4*)Xs;
    for (int i = threadIdx.x; i < GR * (D / 4); i += 256) {
        float4 xv = Xg[i];
        float4 bb = bs4[i & 31];
        xv.x = fmaxf(xv.x + bb.x, 0.f);
        xv.y = fmaxf(xv.y + bb.y, 0.f);
        xv.z = fmaxf(xv.z + bb.z, 0.f);
        xv.w = fmaxf(xv.w + bb.w, 0.f);
        Xs4[i] = xv;
    }
    __syncthreads();

    float a0[5] = {0, 0, 0, 0, 0};
    float a1[5] = {0, 0, 0, 0, 0};
    const float* x0 = Xs + (ty * 2) * D;
#pragma unroll 4
    for (int k = 0; k < D; k++) {
        float w[5];
#pragma unroll
        for (int j = 0; j < 5; j++) w[j] = Ws[k * DOUT + tx * 5 + j];
        float xa = x0[k];
        float xb = x0[D + k];
#pragma unroll
        for (int j = 0; j < 5; j++) {
            a0[j] += xa * w[j];
            a1[j] += xb * w[j];
        }
    }
    int r0 = t0 + ty * 2;
    float* o0 = H3 + (size_t)r0 * DOUT + tx * 5;
#pragma unroll
    for (int j = 0; j < 5; j++) {
        o0[j] = a0[j];
        o0[DOUT + j] = a1[j];
    }
}

// ---------------- aggregation (128-d): fp16 gathers, fp32 accumulate ----------
__global__ __launch_bounds__(256) void k_agg128(const __half2* __restrict__ Hh,
                                                float* __restrict__ Y, int n) {
    __shared__ int   ss[8][32];
    __shared__ float sw[8][32];
    const int lane = threadIdx.x & 31;
    const int wrp  = threadIdx.x >> 5;
    const int i = blockIdx.x * 8 + wrp;
    if (i >= n) return;

    const uint2* __restrict__ Hu = (const uint2*)Hh;   // 32 uint2 per row
    float d2 = g_dis[i]; d2 *= d2;

    // self term
    uint2 su = Hu[(size_t)i * 32 + lane];
    __half2 sh01 = *(__half2*)&su.x;
    __half2 sh23 = *(__half2*)&su.y;
    float2 f01 = __half22float2(sh01);
    float2 f23 = __half22float2(sh23);
    float4 acc = make_float4(d2 * f01.x, d2 * f01.y, d2 * f23.x, d2 * f23.y);

    int p = g_rowptr[i];
    const int pe = g_rowptr[i + 1];
    while (p < pe) {
        int cnt = pe - p;
        if (cnt > 32) cnt = 32;
        if (lane < cnt) {
            ss[wrp][lane] = g_csrc[p + lane];
            sw[wrp][lane] = g_cnorm[p + lane];
        }
        __syncwarp();
#pragma unroll 4
        for (int j = 0; j < cnt; j++) {
            uint2 u = Hu[(size_t)ss[wrp][j] * 32 + lane];
            __half2 h01 = *(__half2*)&u.x;
            __half2 h23 = *(__half2*)&u.y;
            float2 a = __half22float2(h01);
            float2 b = __half22float2(h23);
            float wj = sw[wrp][j];
            acc.x += wj * a.x;
            acc.y += wj * a.y;
            acc.z += wj * b.x;
            acc.w += wj * b.y;
        }
        __syncwarp();
        p += cnt;
    }

    ((float4*)Y)[(size_t)i * 32 + lane] = acc;
}

// ---------------- aggregation (40-d, fp32) + bias + log_softmax + reg ---------
__global__ __launch_bounds__(256) void k_agg40(const float* __restrict__ H3,
                                               const float* __restrict__ b,
                                               float* __restrict__ out, int n,
                                               int reg_idx) {
    if (blockIdx.x == 0 && threadIdx.x == 0) out[reg_idx] = (float)g_reg;

    __shared__ int   ss[8][32];
    __shared__ float sw[8][32];
    const int lane = threadIdx.x & 31;
    const int wrp  = threadIdx.x >> 5;
    const int i = blockIdx.x * 8 + wrp;
    if (i >= n) return;

    float d2 = g_dis[i]; d2 *= d2;
    float a0 = d2 * H3[(size_t)i * DOUT + lane];
    float a1 = (lane < 8) ? d2 * H3[(size_t)i * DOUT + 32 + lane] : 0.f;

    int p = g_rowptr[i];
    const int pe = g_rowptr[i + 1];
    while (p < pe) {
        int cnt = pe - p;
        if (cnt > 32) cnt = 32;
        if (lane < cnt) {
            ss[wrp][lane] = g_csrc[p + lane];
            sw[wrp][lane] = g_cnorm[p + lane];
        }
        __syncwarp();
#pragma unroll 4
        for (int j = 0; j < cnt; j++) {
            int s = ss[wrp][j];
            float wj = sw[wrp][j];
            a0 += wj * H3[(size_t)s * DOUT + lane];
            if (lane < 8) a1 += wj * H3[(size_t)s * DOUT + 32 + lane];
        }
        __syncwarp();
        p += cnt;
    }

    float v0 = a0 + b[lane];
    float v1 = (lane < 8) ? (a1 + b[32 + lane]) : -INFINITY;

    float m = fmaxf(v0, v1);
#pragma unroll
    for (int o = 16; o; o >>= 1) m = fmaxf(m, __shfl_xor_sync(0xffffffffu, m, o));
    float se = expf(v0 - m) + ((lane < 8) ? expf(v1 - m) : 0.f);
#pragma unroll
    for (int o = 16; o; o >>= 1) se += __shfl_xor_sync(0xffffffffu, se, o);
    float ls = m + logf(se);

    out[(size_t)i * DOUT + lane] = v0 - ls;
    if (lane < 8) out[(size_t)i * DOUT + 32 + lane] = v1 - ls;
}

// ---------------- launch --------------------------------------------------------
extern "C" void kernel_launch(void* const* d_in, const int* in_sizes, int n_in,
                              void* d_out, int out_size) {
    const float* x  = (const float*)d_in[0];
    const int*   ei = (const int*)d_in[1];
    const float* W1 = (const float*)d_in[2];
    const float* b1 = (const float*)d_in[3];
    const float* W2 = (const float*)d_in[4];
    const float* b2 = (const float*)d_in[5];
    const float* W3 = (const float*)d_in[6];
    const float* b3 = (const float*)d_in[7];
    float* out = (float*)d_out;

    const int n = in_sizes[0] / D;      // 40000
    const int E = in_sizes[1] / 2;      // 640000
    const int* src = ei;
    const int* dst = ei + E;

    const int GEMM_SMEM = (D * D + GR * D) * sizeof(float);  // 96 KB
    cudaFuncSetAttribute(k_gemm128, cudaFuncAttributeMaxDynamicSharedMemorySize, GEMM_SMEM);

    const int TB = 256;
    const int eblocks = (E + TB - 1) / TB;
    const int ablocks = (n + 7) / 8;
    const int gblocks = (n + GR - 1) / GR;   // 625

    // 1: layer-1 GEMM (fp16 H out)
    k_gemm128<<<gblocks, TB, GEMM_SMEM>>>(x, W1, b1, 0, g_hH, n);
    // 2: in-degree histogram (+ flag reset)
    k_deg<<<eblocks, TB>>>(dst, E);
    // 3: fused graph build (scan + scatter + reverse-edge count)
    k_graph<<<GBB, TB>>>(src, dst, E, n);
    // 4: layer-1 aggregation (fp16 gathers)  <-- PROFILED LAUNCH
    k_agg128<<<ablocks, TB>>>(g_hH, g_y, n);
    // 5-6: layer 2
    k_gemm128<<<gblocks, TB, GEMM_SMEM>>>(g_y, W2, b1, 1, g_hH, n);
    k_agg128<<<ablocks, TB>>>(g_hH, g_y, n);
    // 7-8: layer 3 + log_softmax
    k_gemm40<<<gblocks, TB>>>(g_y, W3, b2, g_h3, n);
    k_agg40<<<ablocks, TB>>>(g_h3, b3, out, n, out_size - 1);
}